// round 9
// baseline (speedup 1.0000x reference)
#include <cuda_runtime.h>

// LatentLinearModel: r[i] = dot(U[users[i]], V[jokes[i]]) + a[users[i]] + b[jokes[i]] + g
// B = 1048576, K = 64.
//
// Round 9: R4 structure, register diet. R4 sat at 44 regs -> 5 blocks/SM
// (register-file cliff: 65536/44/256 = 5.8); smem allows 6. Forcing <=42 regs
// via __launch_bounds__(256,6) seats the 6th block -> +20% in-flight cp.async
// gathers per SM, which is the variable DRAM% has tracked all session.
// Biases now ride 4B cp.asyncs into smem (kills the bias[4] register live
// range and overlaps bias latency with the row gathers).

#define TPR    16                   // threads per row
#define RPG    4                    // rows per 16-lane group
#define BLOCK  256
#define GROUPS (BLOCK / TPR)        // 16
#define RPB    (GROUPS * RPG)       // 64 rows per block

__device__ __forceinline__ void cp_async16(void* smem, const void* gmem) {
    unsigned s = (unsigned)__cvta_generic_to_shared(smem);
    asm volatile("cp.async.cg.shared.global [%0], [%1], 16;" :: "r"(s), "l"(gmem));
}
__device__ __forceinline__ void cp_async4(void* smem, const void* gmem) {
    unsigned s = (unsigned)__cvta_generic_to_shared(smem);
    asm volatile("cp.async.ca.shared.global [%0], [%1], 4;" :: "r"(s), "l"(gmem));
}

__global__ void __launch_bounds__(BLOCK, 6)
latent_linear_kernel(const int* __restrict__ users,
                     const int* __restrict__ jokes,
                     const float4* __restrict__ U4,
                     const float4* __restrict__ V4,
                     const float* __restrict__ a,
                     const float* __restrict__ b,
                     const float* __restrict__ g,
                     float* __restrict__ out,
                     int B) {
    __shared__ float4 sU[RPB][TPR];   // 16 KB
    __shared__ float4 sV[RPB][TPR];   // 16 KB
    __shared__ float  sA[RPB];        // 256 B
    __shared__ float  sB[RPB];        // 256 B

    int lane  = threadIdx.x & (TPR - 1);
    int group = threadIdx.x >> 4;
    int lrow0 = group * RPG;                       // local row base in smem
    int row0  = blockIdx.x * RPB + lrow0;          // global row base
    if (row0 >= B) return;

    // ---- Phase 1: vectorized index loads (row0 multiple of 4 -> 16B aligned) ----
    int4 ui = __ldg((const int4*)(users + row0));
    int4 ji = __ldg((const int4*)(jokes + row0));
    int us[RPG] = {ui.x, ui.y, ui.z, ui.w};
    int js[RPG] = {ji.x, ji.y, ji.z, ji.w};

    // ---- Phase 2: issue all gathers as cp.async (in-flight bytes -> smem) ----
#pragma unroll
    for (int r = 0; r < RPG; r++) {
        cp_async16(&sU[lrow0 + r][lane], &U4[(size_t)us[r] * 16 + lane]);
        cp_async16(&sV[lrow0 + r][lane], &V4[(size_t)js[r] * 16 + lane]);
    }
    // Biases ride the same async group (lane 0 issues; 4B each; L2-resident).
    if (lane == 0) {
#pragma unroll
        for (int r = 0; r < RPG; r++) {
            cp_async4(&sA[lrow0 + r], &a[us[r]]);
            cp_async4(&sB[lrow0 + r], &b[js[r]]);
        }
    }
    asm volatile("cp.async.commit_group;");

    float gg = __ldg(&g[0]);

    asm volatile("cp.async.wait_group 0;" ::: "memory");

    // ---- Phase 3: dot + 16-lane reduction per row (thread-private smem slots) ----
#pragma unroll
    for (int r = 0; r < RPG; r++) {
        float4 uu = sU[lrow0 + r][lane];
        float4 vv = sV[lrow0 + r][lane];
        float d = uu.x * vv.x + uu.y * vv.y + uu.z * vv.z + uu.w * vv.w;
        d += __shfl_xor_sync(0xffffffffu, d, 8);
        d += __shfl_xor_sync(0xffffffffu, d, 4);
        d += __shfl_xor_sync(0xffffffffu, d, 2);
        d += __shfl_xor_sync(0xffffffffu, d, 1);
        if (lane == 0) {
            out[row0 + r] = d + sA[lrow0 + r] + sB[lrow0 + r] + gg;
        }
    }
}

extern "C" void kernel_launch(void* const* d_in, const int* in_sizes, int n_in,
                              void* d_out, int out_size) {
    // metadata order: users, jokes, U, V, a, b, g
    const int*    users = (const int*)d_in[0];
    const int*    jokes = (const int*)d_in[1];
    const float4* U4    = (const float4*)d_in[2];
    const float4* V4    = (const float4*)d_in[3];
    const float*  a     = (const float*)d_in[4];
    const float*  b     = (const float*)d_in[5];
    const float*  g     = (const float*)d_in[6];
    float* out = (float*)d_out;

    int B = in_sizes[0];

    int grid = (B + RPB - 1) / RPB;
    latent_linear_kernel<<<grid, BLOCK>>>(users, jokes, U4, V4, a, b, g, out, B);
}

// round 10
// speedup vs baseline: 1.0127x; 1.0127x over previous
#include <cuda_runtime.h>

// LatentLinearModel: r[i] = dot(U[users[i]], V[jokes[i]]) + a[users[i]] + b[jokes[i]] + g
// B = 1048576, K = 64.
//
// Round 10: deconfounded R4 trim. R9 bundled two changes (6-block launch
// bounds + bias cp.async4) and regressed; the bias cp.asyncs were the culprit
// (extra LSU work inside the commit group). This round keeps R4's body
// EXACTLY (register __ldg biases) and applies only:
//   1) __launch_bounds__(256,6)  - 42-reg target, 6th resident block
//   2) one STG.128 per group for the 4 outputs instead of 4x STG.32
// Everything else is the proven 59.9us configuration.

#define TPR    16                   // threads per row
#define RPG    4                    // rows per 16-lane group
#define BLOCK  256
#define GROUPS (BLOCK / TPR)        // 16
#define RPB    (GROUPS * RPG)       // 64 rows per block

__device__ __forceinline__ void cp_async16(void* smem, const void* gmem) {
    unsigned s = (unsigned)__cvta_generic_to_shared(smem);
    asm volatile("cp.async.cg.shared.global [%0], [%1], 16;" :: "r"(s), "l"(gmem));
}

__global__ void __launch_bounds__(BLOCK, 6)
latent_linear_kernel(const int* __restrict__ users,
                     const int* __restrict__ jokes,
                     const float4* __restrict__ U4,
                     const float4* __restrict__ V4,
                     const float* __restrict__ a,
                     const float* __restrict__ b,
                     const float* __restrict__ g,
                     float* __restrict__ out,
                     int B) {
    __shared__ float4 sU[RPB][TPR];   // 16 KB
    __shared__ float4 sV[RPB][TPR];   // 16 KB

    int lane  = threadIdx.x & (TPR - 1);
    int group = threadIdx.x >> 4;
    int lrow0 = group * RPG;                       // local row base in smem
    int row0  = blockIdx.x * RPB + lrow0;          // global row base
    if (row0 >= B) return;

    // ---- Phase 1: vectorized index loads (row0 multiple of 4 -> 16B aligned) ----
    int4 ui = __ldg((const int4*)(users + row0));
    int4 ji = __ldg((const int4*)(jokes + row0));
    int us[RPG] = {ui.x, ui.y, ui.z, ui.w};
    int js[RPG] = {ji.x, ji.y, ji.z, ji.w};

    // ---- Phase 2: issue all 8 gathers per thread as cp.async (no reg cost) ----
#pragma unroll
    for (int r = 0; r < RPG; r++) {
        cp_async16(&sU[lrow0 + r][lane], &U4[(size_t)us[r] * 16 + lane]);
        cp_async16(&sV[lrow0 + r][lane], &V4[(size_t)js[r] * 16 + lane]);
    }
    asm volatile("cp.async.commit_group;");

    // Bias loads fly concurrently with the cp.asyncs (lane 0 only, registers).
    float bias[RPG];
    if (lane == 0) {
#pragma unroll
        for (int r = 0; r < RPG; r++) {
            bias[r] = __ldg(&a[us[r]]) + __ldg(&b[js[r]]);
        }
    }
    float gg = __ldg(&g[0]);

    asm volatile("cp.async.wait_group 0;" ::: "memory");

    // ---- Phase 3: dot + 16-lane reduction; lane 0 stores all 4 rows as one STG.128 ----
    float res[RPG];
#pragma unroll
    for (int r = 0; r < RPG; r++) {
        float4 uu = sU[lrow0 + r][lane];
        float4 vv = sV[lrow0 + r][lane];
        float d = uu.x * vv.x + uu.y * vv.y + uu.z * vv.z + uu.w * vv.w;
        d += __shfl_xor_sync(0xffffffffu, d, 8);
        d += __shfl_xor_sync(0xffffffffu, d, 4);
        d += __shfl_xor_sync(0xffffffffu, d, 2);
        d += __shfl_xor_sync(0xffffffffu, d, 1);
        res[r] = d;
    }
    if (lane == 0) {
        float4 o;
        o.x = res[0] + bias[0] + gg;
        o.y = res[1] + bias[1] + gg;
        o.z = res[2] + bias[2] + gg;
        o.w = res[3] + bias[3] + gg;
        *(float4*)(out + row0) = o;   // row0 is a multiple of 4 -> 16B aligned
    }
}

extern "C" void kernel_launch(void* const* d_in, const int* in_sizes, int n_in,
                              void* d_out, int out_size) {
    // metadata order: users, jokes, U, V, a, b, g
    const int*    users = (const int*)d_in[0];
    const int*    jokes = (const int*)d_in[1];
    const float4* U4    = (const float4*)d_in[2];
    const float4* V4    = (const float4*)d_in[3];
    const float*  a     = (const float*)d_in[4];
    const float*  b     = (const float*)d_in[5];
    const float*  g     = (const float*)d_in[6];
    float* out = (float*)d_out;

    int B = in_sizes[0];

    int grid = (B + RPB - 1) / RPB;
    latent_linear_kernel<<<grid, BLOCK>>>(users, jokes, U4, V4, a, b, g, out, B);
}

// round 11
// speedup vs baseline: 1.0607x; 1.0474x over previous
#include <cuda_runtime.h>

// LatentLinearModel: r[i] = dot(U[users[i]], V[jokes[i]]) + a[users[i]] + b[jokes[i]] + g
// B = 1048576, K = 64.
//
// FINAL (= Round 4 verbatim, the measured session optimum at 59.9us).
// Evidence across 10 rounds: this random-256B gather saturates at ~61% of
// HBM peak with ~291MB irreducible traffic. The 5-blocks/SM cp.async-to-smem
// configuration exactly fills the per-SM L1tex in-flight queue; every
// perturbation (more MLP, more occupancy, pipelining, persistence, index
// reordering, L2 hints, wider stores) measured equal or worse:
//   R2 65.2 | R3 68.3 | R4 59.9 | R5 61.9 | R6 66.0 | R7 153.6
//   R8 60.2 | R9 63.8 | R10 63.0
//
// Structure: 16 threads cooperate per row (16B/lane -> the 256B row = two
// full 128B lines, zero waste); 4 rows per group; all 8 gathers issued as
// cp.async before any use (in-flight bytes live in smem, not registers);
// wait_group 0; dot + 4-step shfl reduction; coalesced 4B stores.

#define TPR    16                   // threads per row
#define RPG    4                    // rows per 16-lane group
#define BLOCK  256
#define GROUPS (BLOCK / TPR)        // 16
#define RPB    (GROUPS * RPG)       // 64 rows per block

__device__ __forceinline__ void cp_async16(void* smem, const void* gmem) {
    unsigned s = (unsigned)__cvta_generic_to_shared(smem);
    asm volatile("cp.async.cg.shared.global [%0], [%1], 16;" :: "r"(s), "l"(gmem));
}

__global__ void __launch_bounds__(BLOCK)
latent_linear_kernel(const int* __restrict__ users,
                     const int* __restrict__ jokes,
                     const float4* __restrict__ U4,
                     const float4* __restrict__ V4,
                     const float* __restrict__ a,
                     const float* __restrict__ b,
                     const float* __restrict__ g,
                     float* __restrict__ out,
                     int B) {
    __shared__ float4 sU[RPB][TPR];   // 16 KB
    __shared__ float4 sV[RPB][TPR];   // 16 KB

    int lane  = threadIdx.x & (TPR - 1);
    int group = threadIdx.x >> 4;
    int lrow0 = group * RPG;                       // local row base in smem
    int row0  = blockIdx.x * RPB + lrow0;          // global row base
    if (row0 >= B) return;

    // ---- Phase 1: vectorized index loads (row0 multiple of 4 -> 16B aligned) ----
    int4 ui = __ldg((const int4*)(users + row0));
    int4 ji = __ldg((const int4*)(jokes + row0));
    int us[RPG] = {ui.x, ui.y, ui.z, ui.w};
    int js[RPG] = {ji.x, ji.y, ji.z, ji.w};

    // ---- Phase 2: issue all 8 gathers per thread as cp.async (no reg cost) ----
#pragma unroll
    for (int r = 0; r < RPG; r++) {
        cp_async16(&sU[lrow0 + r][lane], &U4[(size_t)us[r] * 16 + lane]);
        cp_async16(&sV[lrow0 + r][lane], &V4[(size_t)js[r] * 16 + lane]);
    }
    asm volatile("cp.async.commit_group;");

    // Bias loads fly concurrently with the cp.asyncs (lane 0 only).
    float bias[RPG];
    if (lane == 0) {
#pragma unroll
        for (int r = 0; r < RPG; r++) {
            bias[r] = __ldg(&a[us[r]]) + __ldg(&b[js[r]]);
        }
    }
    float gg = __ldg(&g[0]);

    asm volatile("cp.async.wait_group 0;" ::: "memory");

    // ---- Phase 3: dot + 16-lane reduction per row (thread-private smem slots) ----
#pragma unroll
    for (int r = 0; r < RPG; r++) {
        float4 uu = sU[lrow0 + r][lane];
        float4 vv = sV[lrow0 + r][lane];
        float d = uu.x * vv.x + uu.y * vv.y + uu.z * vv.z + uu.w * vv.w;
        d += __shfl_xor_sync(0xffffffffu, d, 8);
        d += __shfl_xor_sync(0xffffffffu, d, 4);
        d += __shfl_xor_sync(0xffffffffu, d, 2);
        d += __shfl_xor_sync(0xffffffffu, d, 1);
        if (lane == 0) {
            out[row0 + r] = d + bias[r] + gg;
        }
    }
}

extern "C" void kernel_launch(void* const* d_in, const int* in_sizes, int n_in,
                              void* d_out, int out_size) {
    // metadata order: users, jokes, U, V, a, b, g
    const int*    users = (const int*)d_in[0];
    const int*    jokes = (const int*)d_in[1];
    const float4* U4    = (const float4*)d_in[2];
    const float4* V4    = (const float4*)d_in[3];
    const float*  a     = (const float*)d_in[4];
    const float*  b     = (const float*)d_in[5];
    const float*  g     = (const float*)d_in[6];
    float* out = (float*)d_out;

    int B = in_sizes[0];

    int grid = (B + RPB - 1) / RPB;
    latent_linear_kernel<<<grid, BLOCK>>>(users, jokes, U4, V4, a, b, g, out, B);
}